// round 14
// baseline (speedup 1.0000x reference)
#include <cuda_runtime.h>
#include <cuda_fp16.h>
#include <math.h>
#include <stdint.h>

#define NROWS 4096
#define NC    256
#define TM    32            // rows per fused block
#define KT    16            // k per pipeline stage
#define NSLOT 4             // ring depth

// smem layout (bytes)
#define STG_SZ 13824        // stage: A 32x48 | W 256x48
#define A_OFF  0
#define W_OFF  1536
#define H_OFF   55296       // 4*STG_SZ ; H: 32 rows x 528B
#define RS_OFF  72192       // rowsum[32] float
#define SRC_OFF 72320       // srcbase[32] size_t
#define MB_OFF  72576       // 4 x (full,empty) mbarriers = 64B
#define SMEM_TOTAL 72704

// ---------------- scratch: fp16 weights, TRANSPOSED [N=256, K] layout ----------------
__device__ __align__(16) __half g_W1h[256 * 1792];
__device__ __align__(16) __half g_W2h[3 * 256 * 256];

// ---------------- asm helpers ----------------
__device__ __forceinline__ uint32_t smem_u32(const void* p) {
    uint32_t a;
    asm("{ .reg .u64 t; cvta.to.shared.u64 t, %1; cvt.u32.u64 %0, t; }" : "=r"(a) : "l"(p));
    return a;
}
#define LDSM_X4(r0, r1, r2, r3, addr) \
    asm volatile("ldmatrix.sync.aligned.m8n8.x4.shared.b16 {%0,%1,%2,%3}, [%4];" \
        : "=r"(r0), "=r"(r1), "=r"(r2), "=r"(r3) : "r"(addr))
#define MMA16816(d, a, b0v, b1v) \
    asm volatile("mma.sync.aligned.m16n8k16.row.col.f32.f16.f16.f32 " \
        "{%0,%1,%2,%3}, {%4,%5,%6,%7}, {%8,%9}, {%0,%1,%2,%3};" \
        : "+f"((d)[0]), "+f"((d)[1]), "+f"((d)[2]), "+f"((d)[3]) \
        : "r"((a)[0]), "r"((a)[1]), "r"((a)[2]), "r"((a)[3]), "r"(b0v), "r"(b1v))
#define CP16(dst, src) \
    asm volatile("cp.async.cg.shared.global [%0], [%1], 16;" :: "r"(dst), "l"(src))
#define CP_COMMIT() asm volatile("cp.async.commit_group;" ::: "memory")
#define CP_WAIT0()  asm volatile("cp.async.wait_group 0;" ::: "memory")
#define MBARRIER_INIT(mbar, cnt) \
    asm volatile("mbarrier.init.shared.b64 [%0], %1;" :: "r"((uint32_t)(mbar)), "r"((uint32_t)(cnt)) : "memory")
#define MBARRIER_ARRIVE(mbar) \
    asm volatile("mbarrier.arrive.shared.b64 _, [%0];" :: "r"((uint32_t)(mbar)) : "memory")
#define MBARRIER_WAIT_PARITY(mbar, parity) do { \
    uint32_t _m = (uint32_t)(mbar); uint32_t _p = (uint32_t)(parity); uint32_t _d; \
    asm volatile("{\n\t.reg .pred p;\n\t" \
        "mbarrier.try_wait.parity.acquire.cta.shared::cta.b64 p, [%1], %2;\n\t" \
        "selp.b32 %0, 1, 0, p;\n\t}" : "=r"(_d) : "r"(_m), "r"(_p) : "memory"); \
    if (!_d) { \
        asm volatile("{\n\t.reg .pred P1;\n\t" \
            "WL_%=:\n\t" \
            "mbarrier.try_wait.parity.acquire.cta.shared::cta.b64 P1, [%0], %1, 0x989680;\n\t" \
            "@P1 bra.uni WD_%=;\n\t" \
            "bra.uni WL_%=;\n\t" \
            "WD_%=:\n\t}" :: "r"(_m), "r"(_p) : "memory"); \
    } } while (0)

// ---------------- weight convert: fp32 [K,256] -> fp16 [256,K], strip-wise ----------------
struct WcvtParams {
    const float* W1[3];
    const float* W2[3];
    int    K[3];
    size_t w1off[3];
};

__global__ void wcvt_kernel(WcvtParams p) {
    const int lvl = blockIdx.z;
    const int C = p.K[lvl];
    const int nW1 = C / 32;
    int strip = blockIdx.x;
    const float* W;
    __half* out;
    int K, kb;
    if (strip < nW1) {
        W = p.W1[lvl]; K = C;
        out = g_W1h + p.w1off[lvl];
        kb = strip * 32;
    } else {
        strip -= nW1;
        if (strip >= 8) return;
        W = p.W2[lvl]; K = NC;
        out = g_W2h + (size_t)lvl * 65536;
        kb = strip * 32;
    }
    __shared__ float s[32][257];
    const int tid = threadIdx.x;
#pragma unroll
    for (int j = 0; j < 8; j++) {
        const int job = tid + 256 * j;
        const int r = job >> 6, c4 = job & 63;
        const float4 v = *(const float4*)(W + (size_t)(kb + r) * NC + c4 * 4);
        s[r][c4 * 4 + 0] = v.x;
        s[r][c4 * 4 + 1] = v.y;
        s[r][c4 * 4 + 2] = v.z;
        s[r][c4 * 4 + 3] = v.w;
    }
    __syncthreads();
    const int tx = tid & 31, ty = tid >> 5;
#pragma unroll
    for (int pass = 0; pass < 32; pass++) {
        const int n = pass * 8 + ty;
        out[(size_t)n * K + kb + tx] = __float2half(s[tx][n]);
    }
}

// ---------------- fused gather + MLP + l2norm, warp-specialized ----------------
struct FusedParams {
    const float* feat[3];
    const void*  pid[3];
    const float* bias1[3];
    const float* bias2[3];
    int    C[3];
    int    HW[3];
    size_t w1off[3];
    float* out;
};

// one k16 MMA step; verified mapping (R6..R12)
__device__ __forceinline__ void mma_step16(
    uint32_t aBase, int strA, uint32_t aCol,
    uint32_t wBase, int strW, uint32_t wCol, int lr,
    float (&acc)[8][4])
{
    uint32_t a[4];
    LDSM_X4(a[0], a[1], a[2], a[3], aBase + lr * strA + aCol);
#pragma unroll
    for (int go = 0; go < 2; go++) {
        uint32_t b[2][4];
#pragma unroll
        for (int g = 0; g < 2; g++)
            LDSM_X4(b[g][0], b[g][1], b[g][2], b[g][3],
                    wBase + ((go * 2 + g) * 16 + lr) * strW + wCol);
#pragma unroll
        for (int nl = 0; nl < 4; nl++) {
            const int nb = go * 4 + nl;
            const int g = nl >> 1, h = nl & 1;
            MMA16816(acc[nb], a, b[g][h], b[g][h + 2]);
        }
    }
}

__global__ void __launch_bounds__(288, 3) fused_kernel(FusedParams p) {
    extern __shared__ __align__(16) char dsm[];
    const uint32_t sb = smem_u32(dsm);

    // Longest-job-first flat grid
    const int bx = blockIdx.x;
    const int lvl  = (bx < 128) ? 2 : (bx < 256) ? 1 : 0;
    const int tile = (bx < 128) ? bx : (bx < 256) ? bx - 128 : bx - 256;

    const int K  = p.C[lvl];
    const int HW = p.HW[lvl];
    const int rowBase = tile * TM;
    const int tid = threadIdx.x;
    const int wid = tid >> 5;

    const __half* W1 = g_W1h + p.w1off[lvl];
    const __half* W2 = g_W2h + (size_t)lvl * 65536;
    size_t* srcb = (size_t*)(dsm + SRC_OFF);
    const uint32_t mb = sb + MB_OFF;
    auto mb_full  = [&](int s) { return mb + s * 16; };
    auto mb_empty = [&](int s) { return mb + s * 16 + 8; };

    if (tid == 0) {
#pragma unroll
        for (int s = 0; s < NSLOT; s++) {
            MBARRIER_INIT(mb_full(s), 32);     // producer warp arrivals
            MBARRIER_INIT(mb_empty(s), 256);   // consumer arrivals
        }
    }
    if (tid < TM) *(float*)(dsm + RS_OFF + tid * 4) = 0.0f;
    __syncthreads();   // last block-wide barrier

    const int nk1 = K / KT;          // 16 / 32 / 64
    const int T = nk1 + 16;          // + layer2 W2 stages

    if (wid == 8) {
        // ======================= PRODUCER WARP =======================
        const int ptid = tid - 256;
        const float* feat = p.feat[lvl];
        // srcb (producer-local)
        {
            const int* pw = (const int*)p.pid[lvl];
            bool i64 = true;
#pragma unroll
            for (int i = 1; i < 64; i += 2) i64 = i64 && (pw[i] == 0);
            const int gr = rowBase + ptid;
            long long pid = i64 ? ((const long long*)p.pid[lvl])[gr & 255]
                                : (long long)pw[gr & 255];
            if (pid < 0)  pid = 0;
            if (pid >= HW) pid = HW - 1;
            srcb[ptid] = (size_t)(gr >> 8) * K * HW + (size_t)pid;
            __syncwarp();
        }

        float rg[2][8][2];
        auto ldgA = [&](int t, float (*xg)[2]) {
            const int k0 = t * KT;
#pragma unroll
            for (int j = 0; j < 8; j++) {
                const int pi = ptid + 32 * j;       // 0..255
                const int row = pi >> 3;
                const int c = k0 + (pi & 7) * 2;
                const float* s = feat + srcb[row] + (size_t)c * HW;
                xg[j][0] = __ldcg(s);
                xg[j][1] = __ldcg(s + (size_t)HW);
            }
        };
        auto stsA = [&](int s, float (*xg)[2]) {
#pragma unroll
            for (int j = 0; j < 8; j++) {
                const int pi = ptid + 32 * j;
                const int row = pi >> 3;
                __half2 h = __floats2half2_rn(xg[j][0], xg[j][1]);
                *(uint32_t*)(dsm + s * STG_SZ + A_OFF + row * 48 + (pi & 7) * 4) =
                    *(uint32_t*)&h;
            }
        };
        auto cpW = [&](const __half* Wg, int Kw, int k0, int s) {
#pragma unroll
            for (int j = 0; j < 16; j++) {
                const int job = ptid + 32 * j;      // 0..511
                const int n = job >> 1, ch = job & 1;
                CP16(sb + s * STG_SZ + W_OFF + n * 48 + ch * 16,
                     Wg + (size_t)n * Kw + k0 + ch * 8);
            }
            CP_COMMIT();
        };

        ldgA(0, rg[0]);
        for (int t = 0; t < T; t++) {
            if (t + 1 < nk1) ldgA(t + 1, rg[(t + 1) & 1]);
            const int s = t & 3, r = t >> 2;
            if (t >= NSLOT) MBARRIER_WAIT_PARITY(mb_empty(s), (r - 1) & 1);
            if (t < nk1) { cpW(W1, K, t * KT, s); stsA(s, rg[t & 1]); }
            else         { cpW(W2, 256, (t - nk1) * KT, s); }
            CP_WAIT0();
            MBARRIER_ARRIVE(mb_full(s));
        }
    } else {
        // ======================= CONSUMER WARPS =======================
        const int lid = tid & 31;
        const int lr  = lid & 15;
        const int lcx = (lid >> 4) * 16;
        const int warpM = (wid >> 2) * 16;   // 0 / 16
        const int warpN = (wid & 3) * 64;    // 0..192

        float acc[8][4];
#pragma unroll
        for (int nb = 0; nb < 8; nb++)
#pragma unroll
            for (int j = 0; j < 4; j++) acc[nb][j] = 0.0f;

        // -------- layer 1 --------
        for (int t = 0; t < nk1; t++) {
            const int s = t & 3, r = t >> 2;
            MBARRIER_WAIT_PARITY(mb_full(s), r & 1);
            const uint32_t base = sb + s * STG_SZ;
            mma_step16(base + A_OFF + warpM * 48, 48, lcx,
                       base + W_OFF + warpN * 48, 48, lcx, lr, acc);
            MBARRIER_ARRIVE(mb_empty(s));
        }

        // epilogue-1: bias + relu -> H fp16 smem
        {
            const float* b1 = p.bias1[lvl];
#pragma unroll
            for (int nb = 0; nb < 8; nb++) {
                const int c = warpN + (lid & 3) * 2 + nb * 8;
                const float bx_ = b1[c], by_ = b1[c + 1];
#pragma unroll
                for (int hr = 0; hr < 2; hr++) {
                    const int r = warpM + hr * 8 + (lid >> 2);
                    float v0 = fmaxf(acc[nb][hr * 2]     + bx_, 0.0f);
                    float v1 = fmaxf(acc[nb][hr * 2 + 1] + by_, 0.0f);
                    __half2 h = __floats2half2_rn(v0, v1);
                    *(uint32_t*)(dsm + H_OFF + r * 528 + c * 2) = *(uint32_t*)&h;
                }
            }
        }
        asm volatile("bar.sync 0, 256;" ::: "memory");
#pragma unroll
        for (int nb = 0; nb < 8; nb++)
#pragma unroll
            for (int j = 0; j < 4; j++) acc[nb][j] = 0.0f;

        // -------- layer 2 (A = H smem, W2 from ring) --------
        for (int u = 0; u < 16; u++) {
            const int t = nk1 + u, s = t & 3, r = t >> 2;
            MBARRIER_WAIT_PARITY(mb_full(s), r & 1);
            mma_step16(sb + H_OFF + warpM * 528, 528, u * 32 + lcx,
                       sb + s * STG_SZ + W_OFF + warpN * 48, 48, lcx, lr, acc);
            MBARRIER_ARRIVE(mb_empty(s));
        }

        // epilogue-2: bias, rowwise sum-of-squares, normalize, store
        {
            const float* b2 = p.bias2[lvl];
            float* rowsum = (float*)(dsm + RS_OFF);
#pragma unroll
            for (int hr = 0; hr < 2; hr++) {
                float part = 0.0f;
#pragma unroll
                for (int nb = 0; nb < 8; nb++) {
                    const int c = warpN + (lid & 3) * 2 + nb * 8;
                    float v0 = acc[nb][hr * 2]     + b2[c];
                    float v1 = acc[nb][hr * 2 + 1] + b2[c + 1];
                    acc[nb][hr * 2]     = v0;
                    acc[nb][hr * 2 + 1] = v1;
                    part += v0 * v0 + v1 * v1;
                }
                atomicAdd(&rowsum[warpM + hr * 8 + (lid >> 2)], part);
            }
            asm volatile("bar.sync 0, 256;" ::: "memory");
            float* O = p.out + (size_t)lvl * NROWS * NC;
#pragma unroll
            for (int hr = 0; hr < 2; hr++) {
                const int r = warpM + hr * 8 + (lid >> 2);
                const float sc = 1.0f / (sqrtf(rowsum[r]) + 1e-7f);
#pragma unroll
                for (int nb = 0; nb < 8; nb++) {
                    const int c = warpN + (lid & 3) * 2 + nb * 8;
                    float2 o;
                    o.x = acc[nb][hr * 2]     * sc;
                    o.y = acc[nb][hr * 2 + 1] * sc;
                    *(float2*)(O + (size_t)(rowBase + r) * NC + c) = o;
                }
            }
        }
    }
}

// ---------------- host ----------------
#define F0 67108864LL
#define F1 33554432LL
#define F2 16777216LL
#define W10 65536LL
#define W11 131072LL
#define W12 262144LL
#define SB  256LL

static inline bool ok_sz(long long actual, long long elems) {
    return actual == elems || actual == elems * 4 || actual == elems * 8;
}

extern "C" void kernel_launch(void* const* d_in, const int* in_sizes, int n_in,
                              void* d_out, int out_size) {
    (void)out_size;
    static const int CS[3]  = {256, 512, 1024};
    static const int HWS[3] = {128 * 128, 64 * 64, 32 * 32};
    static const size_t W1OFF[3] = {0, (size_t)256 * 256, (size_t)256 * 768};

    static bool s_attr = false;
    if (!s_attr) {
        cudaFuncSetAttribute(fused_kernel,
                             cudaFuncAttributeMaxDynamicSharedMemorySize, SMEM_TOTAL);
        s_attr = true;
    }

    static const int ORD_DICT[18]  = { 0,1,2,3,4,5,  6,7,8,9,10,11,  12,13,14,15,16,17 };
    static const int ORD_SIG[18]   = { 0,3,6,7,8,9,  1,4,10,11,12,13,  2,5,14,15,16,17 };
    static const int ORD_ALPHA[18] = { 6,9,12,0,15,3,  7,10,13,1,16,4,  8,11,14,2,17,5 };

    const long long featsz[3] = { F0, F1, F2 };
    const long long w1sz[3]   = { W10, W11, W12 };

    const int* cand[3] = { ORD_DICT, ORD_SIG, ORD_ALPHA };
    const int* ord = nullptr;
    for (int c = 0; c < 3 && !ord; c++) {
        bool ok = (n_in >= 18);
        for (int l = 0; l < 3 && ok; l++) {
            const int* m = cand[c] + 6 * l;
            ok = ok && ok_sz(in_sizes[m[0]], featsz[l])
                    && ok_sz(in_sizes[m[1]], SB)
                    && ok_sz(in_sizes[m[2]], w1sz[l])
                    && ok_sz(in_sizes[m[3]], SB)
                    && ok_sz(in_sizes[m[4]], W10)
                    && ok_sz(in_sizes[m[5]], SB);
        }
        if (ok) ord = cand[c];
    }

    int fi[3] = {-1,-1,-1}, pi[3] = {-1,-1,-1}, w1i[3] = {-1,-1,-1};
    int b1i[3] = {-1,-1,-1}, w2i[3] = {-1,-1,-1}, b2i[3] = {-1,-1,-1};
    if (ord) {
        for (int l = 0; l < 3; l++) {
            const int* m = ord + 6 * l;
            fi[l] = m[0]; pi[l] = m[1]; w1i[l] = m[2];
            b1i[l] = m[3]; w2i[l] = m[4]; b2i[l] = m[5];
        }
    } else {
        int any256 = -1, w2seen = 0, w10seen = 0;
        for (int i = 0; i < n_in; i++) {
            long long s = in_sizes[i];
            if      (ok_sz(s, F0))  fi[0] = i;
            else if (ok_sz(s, F1))  fi[1] = i;
            else if (ok_sz(s, F2))  fi[2] = i;
            else if (ok_sz(s, W11)) w1i[1] = i;
            else if (ok_sz(s, W12)) w1i[2] = i;
            else if (ok_sz(s, W10)) {
                if (!w10seen) { w1i[0] = i; w10seen = 1; }
                else if (w2seen < 3) w2i[w2seen++] = i;
            }
            else if (ok_sz(s, SB) && any256 < 0) any256 = i;
        }
        for (int l = 0; l < 3; l++) {
            if (fi[l] >= 0) {
                int nxt = fi[l] + 1;
                pi[l] = (nxt < n_in && ok_sz(in_sizes[nxt], SB)) ? nxt : any256;
            }
            b1i[l] = any256; b2i[l] = any256;
        }
    }
    for (int l = 0; l < 3; l++) {
        if (fi[l] < 0 || pi[l] < 0 || w1i[l] < 0 || b1i[l] < 0 ||
            w2i[l] < 0 || b2i[l] < 0) return;
    }

    WcvtParams wc;
    FusedParams fp;
    for (int i = 0; i < 3; i++) {
        wc.W1[i] = (const float*)d_in[w1i[i]];
        wc.W2[i] = (const float*)d_in[w2i[i]];
        wc.K[i]  = CS[i];
        wc.w1off[i] = W1OFF[i];

        fp.feat[i]  = (const float*)d_in[fi[i]];
        fp.pid[i]   = d_in[pi[i]];
        fp.bias1[i] = (const float*)d_in[b1i[i]];
        fp.bias2[i] = (const float*)d_in[b2i[i]];
        fp.C[i]     = CS[i];
        fp.HW[i]    = HWS[i];
        fp.w1off[i] = W1OFF[i];
    }
    fp.out = (float*)d_out;

    wcvt_kernel<<<dim3(40, 1, 3), 256>>>(wc);

    fused_kernel<<<384, 288, SMEM_TOTAL>>>(fp);
}

// round 15
// speedup vs baseline: 1.5789x; 1.5789x over previous
#include <cuda_runtime.h>
#include <cuda_fp16.h>
#include <math.h>
#include <stdint.h>

#define NROWS 4096
#define NC    256
#define TM    32            // rows per MLP block
#define KT    32            // k per pipeline stage

// smem layout (bytes)
#define STG    23040        // stage: A 32x80 | W 256x80
#define A_OFF  0
#define W_OFF  2560
#define H_OFF  46080        // H: 32 rows x 528B
#define RS_OFF 62976        // rowsum[32] float
#define SMEM_TOTAL 63360

// ---------------- scratch ----------------
__device__ __align__(16) __half g_Xh[4096 * 1792];          // gathered X, fp16
__device__ __align__(16) __half g_W1h[256 * 1792];          // W1^T fp16 [N,K]
__device__ __align__(16) __half g_W2h[3 * 256 * 256];       // W2^T fp16 [N,256]

// ---------------- asm helpers ----------------
__device__ __forceinline__ uint32_t smem_u32(const void* p) {
    uint32_t a;
    asm("{ .reg .u64 t; cvta.to.shared.u64 t, %1; cvt.u32.u64 %0, t; }" : "=r"(a) : "l"(p));
    return a;
}
#define LDSM_X4(r0, r1, r2, r3, addr) \
    asm volatile("ldmatrix.sync.aligned.m8n8.x4.shared.b16 {%0,%1,%2,%3}, [%4];" \
        : "=r"(r0), "=r"(r1), "=r"(r2), "=r"(r3) : "r"(addr))
#define MMA16816(d, a, b0v, b1v) \
    asm volatile("mma.sync.aligned.m16n8k16.row.col.f32.f16.f16.f32 " \
        "{%0,%1,%2,%3}, {%4,%5,%6,%7}, {%8,%9}, {%0,%1,%2,%3};" \
        : "+f"((d)[0]), "+f"((d)[1]), "+f"((d)[2]), "+f"((d)[3]) \
        : "r"((a)[0]), "r"((a)[1]), "r"((a)[2]), "r"((a)[3]), "r"(b0v), "r"(b1v))
#define CP16(dst, src) \
    asm volatile("cp.async.cg.shared.global [%0], [%1], 16;" :: "r"(dst), "l"(src))
#define CP_COMMIT() asm volatile("cp.async.commit_group;" ::: "memory")
#define CP_WAIT0()  asm volatile("cp.async.wait_group 0;" ::: "memory")
#define CP_WAIT1()  asm volatile("cp.async.wait_group 1;" ::: "memory")

// ---------------- prep: gather (fp32->fp16) + weight convert, one kernel ----------------
struct PrepParams {
    const float* feat[3];
    const void*  pid[3];
    const float* W1[3];
    const float* W2[3];
    int    C[3];
    int    HW[3];
    size_t xoff[3];
    size_t w1off[3];
};

__global__ void prep_kernel(PrepParams p) {
    const int lvl = blockIdx.z;
    const int C   = p.C[lvl];
    const int bx  = blockIdx.x;
    const int tid = threadIdx.x;

    if (bx < 512) {
        // ---- gather: warp per row, lanes hold 2*nj independent LDGs ----
        const int w = tid >> 5, l = tid & 31;
        const int row = bx * 8 + w;
        const int HW = p.HW[lvl];
        const int* pw = (const int*)p.pid[lvl];
        bool i64 = true;
#pragma unroll
        for (int i = 1; i < 64; i += 2) i64 = i64 && (pw[i] == 0);
        long long pid = i64 ? ((const long long*)p.pid[lvl])[row & 255]
                            : (long long)pw[row & 255];
        if (pid < 0)  pid = 0;
        if (pid >= HW) pid = HW - 1;
        const float* src = p.feat[lvl] + (size_t)(row >> 8) * C * HW + (size_t)pid;
        __half* dst = g_Xh + p.xoff[lvl] + (size_t)row * C;

        const int nj = C >> 6;                  // 4 / 8 / 16
        float xa[16], xb[16];
#pragma unroll 16
        for (int j = 0; j < 16; j++) {
            if (j < nj) {
                const int c = 2 * l + 64 * j;
                xa[j] = __ldcg(src + (size_t)c * HW);
                xb[j] = __ldcg(src + (size_t)(c + 1) * HW);
            }
        }
#pragma unroll 16
        for (int j = 0; j < 16; j++) {
            if (j < nj) {
                const int c = 2 * l + 64 * j;
                __half2 h = __floats2half2_rn(xa[j], xb[j]);
                *(__half2*)(dst + c) = h;
            }
        }
        return;
    }

    // ---- weight transform: W[K,256] -> [N=256,K] fp16, strip-wise ----
    int strip = bx - 512;
    const int nW1 = C / 32;
    const float* W;
    __half* out;
    int K, kb;
    if (strip < nW1) {
        W = p.W1[lvl]; K = C;
        out = g_W1h + p.w1off[lvl];
        kb = strip * 32;
    } else {
        strip -= nW1;
        if (strip >= 8) return;
        W = p.W2[lvl]; K = NC;
        out = g_W2h + (size_t)lvl * 65536;
        kb = strip * 32;
    }
    __shared__ float s[32][257];
#pragma unroll
    for (int j = 0; j < 8; j++) {
        const int job = tid + 256 * j;
        const int r = job >> 6, c4 = job & 63;
        const float4 v = *(const float4*)(W + (size_t)(kb + r) * NC + c4 * 4);
        s[r][c4 * 4 + 0] = v.x;
        s[r][c4 * 4 + 1] = v.y;
        s[r][c4 * 4 + 2] = v.z;
        s[r][c4 * 4 + 3] = v.w;
    }
    __syncthreads();
    const int tx = tid & 31, ty = tid >> 5;
#pragma unroll
    for (int pass = 0; pass < 32; pass++) {
        const int n = pass * 8 + ty;
        out[(size_t)n * K + kb + tx] = __float2half(s[tx][n]);
    }
}

// ---------------- MLP kernel (GEMM+GEMM+l2norm), A from g_Xh via cp.async ----------------
struct MlpParams {
    const float* bias1[3];
    const float* bias2[3];
    int    C[3];
    size_t xoff[3];
    size_t w1off[3];
    float* out;
};

// verified MMA mapping (R6..R12)
__device__ __forceinline__ void mma_step16(
    uint32_t aBase, int strA, uint32_t aCol,
    uint32_t wBase, int strW, uint32_t wCol, int lr,
    float (&acc)[8][4])
{
    uint32_t a[4];
    LDSM_X4(a[0], a[1], a[2], a[3], aBase + lr * strA + aCol);
#pragma unroll
    for (int go = 0; go < 2; go++) {
        uint32_t b[2][4];
#pragma unroll
        for (int g = 0; g < 2; g++)
            LDSM_X4(b[g][0], b[g][1], b[g][2], b[g][3],
                    wBase + ((go * 2 + g) * 16 + lr) * strW + wCol);
#pragma unroll
        for (int nl = 0; nl < 4; nl++) {
            const int nb = go * 4 + nl;
            const int g = nl >> 1, h = nl & 1;
            MMA16816(acc[nb], a, b[g][h], b[g][h + 2]);
        }
    }
}

__global__ void __launch_bounds__(256, 3) mlp_kernel(MlpParams p) {
    extern __shared__ __align__(16) char dsm[];
    const uint32_t sb = smem_u32(dsm);

    // longest-job-first flat grid
    const int bx = blockIdx.x;
    const int lvl  = (bx < 128) ? 2 : (bx < 256) ? 1 : 0;
    const int tile = (bx < 128) ? bx : (bx < 256) ? bx - 128 : bx - 256;

    const int K = p.C[lvl];
    const int rowBase = tile * TM;
    const int tid = threadIdx.x;
    const int wid = tid >> 5;
    const int lid = tid & 31;
    const int lr  = lid & 15;
    const int lcx = (lid >> 4) * 16;
    const int warpM = (wid >> 2) * 16;   // 0 / 16
    const int warpN = (wid & 3) * 64;    // 0..192

    const __half* Xr = g_Xh + p.xoff[lvl] + (size_t)rowBase * K;
    const __half* W1 = g_W1h + p.w1off[lvl];
    const __half* W2 = g_W2h + (size_t)lvl * 65536;

    if (tid < TM) *(float*)(dsm + RS_OFF + tid * 4) = 0.0f;
    __syncthreads();

    // A stage: 32 rows x 32k fp16 = 128 x 16B chunks, threads 0-127
    auto loadA = [&](int t, int buf) {
        if (tid < 128) {
            const int r = tid >> 2, ch = tid & 3;
            CP16(sb + buf * STG + A_OFF + r * 80 + ch * 16,
                 Xr + (size_t)r * K + t * KT + ch * 8);
        }
    };
    // W stage: 256 n-rows x 32 k fp16 = 1024 x 16B chunks, 4/thread
    auto loadW = [&](const __half* Wg, int Kw, int t, int buf) {
#pragma unroll
        for (int j = 0; j < 4; j++) {
            const int job = tid + 256 * j;
            const int n = job >> 2, ch = job & 3;
            CP16(sb + buf * STG + W_OFF + n * 80 + ch * 16,
                 Wg + (size_t)n * Kw + t * KT + ch * 8);
        }
    };

    float acc[8][4];
#pragma unroll
    for (int nb = 0; nb < 8; nb++)
#pragma unroll
        for (int j = 0; j < 4; j++) acc[nb][j] = 0.0f;

    // ================= layer 1 =================
    const int nk1 = K / KT;     // 8 / 16 / 32
    loadA(0, 0); loadW(W1, K, 0, 0); CP_COMMIT();
    for (int t = 0; t < nk1; t++) {
        const int buf = t & 1;
        if (t + 1 < nk1) {
            loadA(t + 1, buf ^ 1); loadW(W1, K, t + 1, buf ^ 1); CP_COMMIT();
            CP_WAIT1();
        } else {
            CP_WAIT0();
        }
        __syncthreads();
        const uint32_t base = sb + buf * STG;
#pragma unroll
        for (int kk = 0; kk < 2; kk++)
            mma_step16(base + A_OFF + warpM * 80, 80, kk * 32 + lcx,
                       base + W_OFF + warpN * 80, 80, kk * 32 + lcx, lr, acc);
        __syncthreads();
    }

    // prefetch W2 stage 0 (nk1 even -> buf0 free); epilogue-1: bias+relu -> H fp16
    loadW(W2, 256, 0, 0); CP_COMMIT();
    {
        const float* b1 = p.bias1[lvl];
#pragma unroll
        for (int nb = 0; nb < 8; nb++) {
            const int c = warpN + (lid & 3) * 2 + nb * 8;
            const float bx_ = b1[c], by_ = b1[c + 1];
#pragma unroll
            for (int hr = 0; hr < 2; hr++) {
                const int r = warpM + hr * 8 + (lid >> 2);
                float v0 = fmaxf(acc[nb][hr * 2]     + bx_, 0.0f);
                float v1 = fmaxf(acc[nb][hr * 2 + 1] + by_, 0.0f);
                __half2 h = __floats2half2_rn(v0, v1);
                *(uint32_t*)(dsm + H_OFF + r * 528 + c * 2) = *(uint32_t*)&h;
            }
        }
    }
#pragma unroll
    for (int nb = 0; nb < 8; nb++)
#pragma unroll
        for (int j = 0; j < 4; j++) acc[nb][j] = 0.0f;

    // ================= layer 2 (A = H smem, 8 stages) ==========
    for (int t = 0; t < 8; t++) {
        const int buf = t & 1;
        if (t + 1 < 8) { loadW(W2, 256, t + 1, buf ^ 1); CP_COMMIT(); CP_WAIT1(); }
        else           { CP_WAIT0(); }
        __syncthreads();
        const uint32_t base = sb + buf * STG;
#pragma unroll
        for (int kk = 0; kk < 2; kk++)
            mma_step16(sb + H_OFF + warpM * 528, 528, (t * 32 + kk * 16) * 2 + lcx,
                       base + W_OFF + warpN * 80, 80, kk * 32 + lcx, lr, acc);
        __syncthreads();
    }

    // ============ epilogue-2: bias, row sum-of-squares, normalize, store =====
    {
        const float* b2 = p.bias2[lvl];
        float* rowsum = (float*)(dsm + RS_OFF);
#pragma unroll
        for (int hr = 0; hr < 2; hr++) {
            float part = 0.0f;
#pragma unroll
            for (int nb = 0; nb < 8; nb++) {
                const int c = warpN + (lid & 3) * 2 + nb * 8;
                float v0 = acc[nb][hr * 2]     + b2[c];
                float v1 = acc[nb][hr * 2 + 1] + b2[c + 1];
                acc[nb][hr * 2]     = v0;
                acc[nb][hr * 2 + 1] = v1;
                part += v0 * v0 + v1 * v1;
            }
            atomicAdd(&rowsum[warpM + hr * 8 + (lid >> 2)], part);
        }
        __syncthreads();
        float* O = p.out + (size_t)lvl * NROWS * NC;
#pragma unroll
        for (int hr = 0; hr < 2; hr++) {
            const int r = warpM + hr * 8 + (lid >> 2);
            const float sc = 1.0f / (sqrtf(rowsum[r]) + 1e-7f);
#pragma unroll
            for (int nb = 0; nb < 8; nb++) {
                const int c = warpN + (lid & 3) * 2 + nb * 8;
                float2 o;
                o.x = acc[nb][hr * 2]     * sc;
                o.y = acc[nb][hr * 2 + 1] * sc;
                *(float2*)(O + (size_t)(rowBase + r) * NC + c) = o;
            }
        }
    }
}

// ---------------- host ----------------
#define F0 67108864LL
#define F1 33554432LL
#define F2 16777216LL
#define W10 65536LL
#define W11 131072LL
#define W12 262144LL
#define SB  256LL

static inline bool ok_sz(long long actual, long long elems) {
    return actual == elems || actual == elems * 4 || actual == elems * 8;
}

extern "C" void kernel_launch(void* const* d_in, const int* in_sizes, int n_in,
                              void* d_out, int out_size) {
    (void)out_size;
    static const int CS[3]  = {256, 512, 1024};
    static const int HWS[3] = {128 * 128, 64 * 64, 32 * 32};
    static const size_t XOFF[3]  = {0, (size_t)4096 * 256, (size_t)4096 * 768};
    static const size_t W1OFF[3] = {0, (size_t)256 * 256, (size_t)256 * 768};

    static bool s_attr = false;
    if (!s_attr) {
        cudaFuncSetAttribute(mlp_kernel,
                             cudaFuncAttributeMaxDynamicSharedMemorySize, SMEM_TOTAL);
        s_attr = true;
    }

    static const int ORD_DICT[18]  = { 0,1,2,3,4,5,  6,7,8,9,10,11,  12,13,14,15,16,17 };
    static const int ORD_SIG[18]   = { 0,3,6,7,8,9,  1,4,10,11,12,13,  2,5,14,15,16,17 };
    static const int ORD_ALPHA[18] = { 6,9,12,0,15,3,  7,10,13,1,16,4,  8,11,14,2,17,5 };

    const long long featsz[3] = { F0, F1, F2 };
    const long long w1sz[3]   = { W10, W11, W12 };

    const int* cand[3] = { ORD_DICT, ORD_SIG, ORD_ALPHA };
    const int* ord = nullptr;
    for (int c = 0; c < 3 && !ord; c++) {
        bool ok = (n_in >= 18);
        for (int l = 0; l < 3 && ok; l++) {
            const int* m = cand[c] + 6 * l;
            ok = ok && ok_sz(in_sizes[m[0]], featsz[l])
                    && ok_sz(in_sizes[m[1]], SB)
                    && ok_sz(in_sizes[m[2]], w1sz[l])
                    && ok_sz(in_sizes[m[3]], SB)
                    && ok_sz(in_sizes[m[4]], W10)
                    && ok_sz(in_sizes[m[5]], SB);
        }
        if (ok) ord = cand[c];
    }

    int fi[3] = {-1,-1,-1}, pi[3] = {-1,-1,-1}, w1i[3] = {-1,-1,-1};
    int b1i[3] = {-1,-1,-1}, w2i[3] = {-1,-1,-1}, b2i[3] = {-1,-1,-1};
    if (ord) {
        for (int l = 0; l < 3; l++) {
            const int* m = ord + 6 * l;
            fi[l] = m[0]; pi[l] = m[1]; w1i[l] = m[2];
            b1i[l] = m[3]; w2i[l] = m[4]; b2i[l] = m[5];
        }
    } else {
        int any256 = -1, w2seen = 0, w10seen = 0;
        for (int i = 0; i < n_in; i++) {
            long long s = in_sizes[i];
            if      (ok_sz(s, F0))  fi[0] = i;
            else if (ok_sz(s, F1))  fi[1] = i;
            else if (ok_sz(s, F2))  fi[2] = i;
            else if (ok_sz(s, W11)) w1i[1] = i;
            else if (ok_sz(s, W12)) w1i[2] = i;
            else if (ok_sz(s, W10)) {
                if (!w10seen) { w1i[0] = i; w10seen = 1; }
                else if (w2seen < 3) w2i[w2seen++] = i;
            }
            else if (ok_sz(s, SB) && any256 < 0) any256 = i;
        }
        for (int l = 0; l < 3; l++) {
            if (fi[l] >= 0) {
                int nxt = fi[l] + 1;
                pi[l] = (nxt < n_in && ok_sz(in_sizes[nxt], SB)) ? nxt : any256;
            }
            b1i[l] = any256; b2i[l] = any256;
        }
    }
    for (int l = 0; l < 3; l++) {
        if (fi[l] < 0 || pi[l] < 0 || w1i[l] < 0 || b1i[l] < 0 ||
            w2i[l] < 0 || b2i[l] < 0) return;
    }

    PrepParams pp;
    MlpParams mp;
    for (int i = 0; i < 3; i++) {
        pp.feat[i] = (const float*)d_in[fi[i]];
        pp.pid[i]  = d_in[pi[i]];
        pp.W1[i]   = (const float*)d_in[w1i[i]];
        pp.W2[i]   = (const float*)d_in[w2i[i]];
        pp.C[i]    = CS[i];
        pp.HW[i]   = HWS[i];
        pp.xoff[i] = XOFF[i];
        pp.w1off[i] = W1OFF[i];

        mp.bias1[i] = (const float*)d_in[b1i[i]];
        mp.bias2[i] = (const float*)d_in[b2i[i]];
        mp.C[i]     = CS[i];
        mp.xoff[i]  = XOFF[i];
        mp.w1off[i] = W1OFF[i];
    }
    mp.out = (float*)d_out;

    // prep: 512 gather blocks + up to 40 wcvt strips, per level
    prep_kernel<<<dim3(512 + 40, 1, 3), 256>>>(pp);

    mlp_kernel<<<384, 256, SMEM_TOTAL>>>(mp);
}

// round 16
// speedup vs baseline: 2.1755x; 1.3778x over previous
#include <cuda_runtime.h>
#include <cuda_fp16.h>
#include <math.h>
#include <stdint.h>

#define NROWS 4096
#define NC    256
#define TM    64            // rows per MLP block
#define KT    32            // k per pipeline stage

// smem layout (bytes)
#define STG    25600        // stage: A 64x80 | W 256x80
#define A_OFF  0
#define W_OFF  5120
#define H_OFF  51200        // H: 64 rows x 528B
#define RS_OFF 84992        // rowsum[64] float
#define SMEM_TOTAL 85248

// ---------------- scratch ----------------
__device__ __align__(16) __half g_Xh[4096 * 1792];          // gathered X, fp16
__device__ __align__(16) __half g_W1h[256 * 1792];          // W1^T fp16 [N,K]
__device__ __align__(16) __half g_W2h[3 * 256 * 256];       // W2^T fp16 [N,256]

// ---------------- asm helpers ----------------
__device__ __forceinline__ uint32_t smem_u32(const void* p) {
    uint32_t a;
    asm("{ .reg .u64 t; cvta.to.shared.u64 t, %1; cvt.u32.u64 %0, t; }" : "=r"(a) : "l"(p));
    return a;
}
#define LDSM_X4(r0, r1, r2, r3, addr) \
    asm volatile("ldmatrix.sync.aligned.m8n8.x4.shared.b16 {%0,%1,%2,%3}, [%4];" \
        : "=r"(r0), "=r"(r1), "=r"(r2), "=r"(r3) : "r"(addr))
#define MMA16816(d, a, b0v, b1v) \
    asm volatile("mma.sync.aligned.m16n8k16.row.col.f32.f16.f16.f32 " \
        "{%0,%1,%2,%3}, {%4,%5,%6,%7}, {%8,%9}, {%0,%1,%2,%3};" \
        : "+f"((d)[0]), "+f"((d)[1]), "+f"((d)[2]), "+f"((d)[3]) \
        : "r"((a)[0]), "r"((a)[1]), "r"((a)[2]), "r"((a)[3]), "r"(b0v), "r"(b1v))
#define CP16(dst, src) \
    asm volatile("cp.async.cg.shared.global [%0], [%1], 16;" :: "r"(dst), "l"(src))
#define CP_COMMIT() asm volatile("cp.async.commit_group;" ::: "memory")
#define CP_WAIT0()  asm volatile("cp.async.wait_group 0;" ::: "memory")
#define CP_WAIT1()  asm volatile("cp.async.wait_group 1;" ::: "memory")

// ---------------- prep: wcvt strips first, then LJF gather ----------------
struct PrepParams {
    const float* feat[3];
    const void*  pid[3];
    const float* W1[3];
    const float* W2[3];
    int    C[3];
    int    HW[3];
    size_t xoff[3];
    size_t w1off[3];
};

// flat grid: [0,80) wcvt strips (lvl2 first), [80,592) lvl2 gather,
// [592,1104) lvl1 gather, [1104,1616) lvl0 gather.
__global__ void prep_kernel(PrepParams p) {
    const int bx  = blockIdx.x;
    const int tid = threadIdx.x;

    if (bx < 80) {
        // ---- weight transform strips; LJF: lvl2 (40), lvl1 (24), lvl0 (16) ----
        int lvl, strip;
        if (bx < 40)      { lvl = 2; strip = bx; }
        else if (bx < 64) { lvl = 1; strip = bx - 40; }
        else              { lvl = 0; strip = bx - 64; }
        const int C = p.C[lvl];
        const int nW1 = C / 32;
        const float* W;
        __half* out;
        int K, kb;
        if (strip < nW1) {
            W = p.W1[lvl]; K = C;
            out = g_W1h + p.w1off[lvl];
            kb = strip * 32;
        } else {
            strip -= nW1;
            W = p.W2[lvl]; K = NC;
            out = g_W2h + (size_t)lvl * 65536;
            kb = strip * 32;
        }
        __shared__ float s[32][257];
#pragma unroll
        for (int j = 0; j < 8; j++) {
            const int job = tid + 256 * j;
            const int r = job >> 6, c4 = job & 63;
            const float4 v = *(const float4*)(W + (size_t)(kb + r) * NC + c4 * 4);
            s[r][c4 * 4 + 0] = v.x;
            s[r][c4 * 4 + 1] = v.y;
            s[r][c4 * 4 + 2] = v.z;
            s[r][c4 * 4 + 3] = v.w;
        }
        __syncthreads();
        const int tx = tid & 31, ty = tid >> 5;
#pragma unroll
        for (int pass = 0; pass < 32; pass++) {
            const int n = pass * 8 + ty;
            out[(size_t)n * K + kb + tx] = __float2half(s[tx][n]);
        }
        return;
    }

    // ---- gather, LJF: lvl2 blocks first ----
    const int g = bx - 80;
    const int lvl = (g < 512) ? 2 : (g < 1024) ? 1 : 0;
    const int gb  = (g < 512) ? g : (g < 1024) ? g - 512 : g - 1024;
    const int C  = p.C[lvl];
    const int HW = p.HW[lvl];

    const int w = tid >> 5, l = tid & 31;
    const int row = gb * 8 + w;
    const int* pw = (const int*)p.pid[lvl];
    bool i64 = true;
#pragma unroll
    for (int i = 1; i < 64; i += 2) i64 = i64 && (pw[i] == 0);
    long long pid = i64 ? ((const long long*)p.pid[lvl])[row & 255]
                        : (long long)pw[row & 255];
    if (pid < 0)  pid = 0;
    if (pid >= HW) pid = HW - 1;
    const float* src = p.feat[lvl] + (size_t)(row >> 8) * C * HW + (size_t)pid;
    __half* dst = g_Xh + p.xoff[lvl] + (size_t)row * C;

    const int nj = C >> 6;                  // 4 / 8 / 16
    float xa[16], xb[16];
#pragma unroll 16
    for (int j = 0; j < 16; j++) {
        if (j < nj) {
            const int c = 2 * l + 64 * j;
            xa[j] = __ldcg(src + (size_t)c * HW);
            xb[j] = __ldcg(src + (size_t)(c + 1) * HW);
        }
    }
#pragma unroll 16
    for (int j = 0; j < 16; j++) {
        if (j < nj) {
            const int c = 2 * l + 64 * j;
            __half2 h = __floats2half2_rn(xa[j], xb[j]);
            *(__half2*)(dst + c) = h;
        }
    }
}

// ---------------- MLP kernel, TM=64, 512 threads ----------------
struct MlpParams {
    const float* bias1[3];
    const float* bias2[3];
    int    C[3];
    size_t xoff[3];
    size_t w1off[3];
    float* out;
};

// verified MMA mapping (R6..R14)
__device__ __forceinline__ void mma_step16(
    uint32_t aBase, int strA, uint32_t aCol,
    uint32_t wBase, int strW, uint32_t wCol, int lr,
    float (&acc)[8][4])
{
    uint32_t a[4];
    LDSM_X4(a[0], a[1], a[2], a[3], aBase + lr * strA + aCol);
#pragma unroll
    for (int go = 0; go < 2; go++) {
        uint32_t b[2][4];
#pragma unroll
        for (int g = 0; g < 2; g++)
            LDSM_X4(b[g][0], b[g][1], b[g][2], b[g][3],
                    wBase + ((go * 2 + g) * 16 + lr) * strW + wCol);
#pragma unroll
        for (int nl = 0; nl < 4; nl++) {
            const int nb = go * 4 + nl;
            const int g = nl >> 1, h = nl & 1;
            MMA16816(acc[nb], a, b[g][h], b[g][h + 2]);
        }
    }
}

__global__ void __launch_bounds__(512, 2) mlp_kernel(MlpParams p) {
    extern __shared__ __align__(16) char dsm[];
    const uint32_t sb = smem_u32(dsm);

    // longest-job-first flat grid: 64 blocks per level
    const int bx = blockIdx.x;
    const int lvl  = (bx < 64) ? 2 : (bx < 128) ? 1 : 0;
    const int tile = (bx < 64) ? bx : (bx < 128) ? bx - 64 : bx - 128;

    const int K = p.C[lvl];
    const int rowBase = tile * TM;
    const int tid = threadIdx.x;
    const int wid = tid >> 5;            // 0..15
    const int lid = tid & 31;
    const int lr  = lid & 15;
    const int lcx = (lid >> 4) * 16;
    const int warpM = (wid >> 2) * 16;   // 0..48
    const int warpN = (wid & 3) * 64;    // 0..192

    const __half* Xr = g_Xh + p.xoff[lvl] + (size_t)rowBase * K;
    const __half* W1 = g_W1h + p.w1off[lvl];
    const __half* W2 = g_W2h + (size_t)lvl * 65536;

    if (tid < TM) *(float*)(dsm + RS_OFF + tid * 4) = 0.0f;
    __syncthreads();

    // A stage: 64 rows x 32k fp16 = 256 x 16B chunks, threads 0-255
    auto loadA = [&](int t, int buf) {
        if (tid < 256) {
            const int r = tid >> 2, ch = tid & 3;
            CP16(sb + buf * STG + A_OFF + r * 80 + ch * 16,
                 Xr + (size_t)r * K + t * KT + ch * 8);
        }
    };
    // W stage: 256 n-rows x 32 k fp16 = 1024 x 16B chunks, 2/thread
    auto loadW = [&](const __half* Wg, int Kw, int t, int buf) {
#pragma unroll
        for (int j = 0; j < 2; j++) {
            const int job = tid + 512 * j;
            const int n = job >> 2, ch = job & 3;
            CP16(sb + buf * STG + W_OFF + n * 80 + ch * 16,
                 Wg + (size_t)n * Kw + t * KT + ch * 8);
        }
    };

    float acc[8][4];
#pragma unroll
    for (int nb = 0; nb < 8; nb++)
#pragma unroll
        for (int j = 0; j < 4; j++) acc[nb][j] = 0.0f;

    // ================= layer 1 =================
    const int nk1 = K / KT;     // 8 / 16 / 32
    loadA(0, 0); loadW(W1, K, 0, 0); CP_COMMIT();
    for (int t = 0; t < nk1; t++) {
        const int buf = t & 1;
        if (t + 1 < nk1) {
            loadA(t + 1, buf ^ 1); loadW(W1, K, t + 1, buf ^ 1); CP_COMMIT();
            CP_WAIT1();
        } else {
            CP_WAIT0();
        }
        __syncthreads();
        const uint32_t base = sb + buf * STG;
#pragma unroll
        for (int kk = 0; kk < 2; kk++)
            mma_step16(base + A_OFF + warpM * 80, 80, kk * 32 + lcx,
                       base + W_OFF + warpN * 80, 80, kk * 32 + lcx, lr, acc);
        __syncthreads();
    }

    // prefetch W2 stage 0 (nk1 even -> buf0 free); epilogue-1: bias+relu -> H fp16
    loadW(W2, 256, 0, 0); CP_COMMIT();
    {
        const float* b1 = p.bias1[lvl];
#pragma unroll
        for (int nb = 0; nb < 8; nb++) {
            const int c = warpN + (lid & 3) * 2 + nb * 8;
            const float bx_ = b1[c], by_ = b1[c + 1];
#pragma unroll
            for (int hr = 0; hr < 2; hr++) {
                const int r = warpM + hr * 8 + (lid >> 2);
                float v0 = fmaxf(acc[nb][hr * 2]     + bx_, 0.0f);
                float v1 = fmaxf(acc[nb][hr * 2 + 1] + by_, 0.0f);
                __half2 h = __floats2half2_rn(v0, v1);
                *(uint32_t*)(dsm + H_OFF + r * 528 + c * 2) = *(uint32_t*)&h;
            }
        }
    }
#pragma unroll
    for (int nb = 0; nb < 8; nb++)
#pragma unroll
        for (int j = 0; j < 4; j++) acc[nb][j] = 0.0f;

    // ================= layer 2 (A = H smem, 8 stages) ==========
    for (int t = 0; t < 8; t++) {
        const int buf = t & 1;
        if (t + 1 < 8) { loadW(W2, 256, t + 1, buf ^ 1); CP_COMMIT(); CP_WAIT1(); }
        else           { CP_WAIT0(); }
        __syncthreads();
        const uint32_t base = sb + buf * STG;
#pragma unroll
        for (int kk = 0; kk < 2; kk++)
            mma_step16(sb + H_OFF + warpM * 528, 528, (t * 32 + kk * 16) * 2 + lcx,
                       base + W_OFF + warpN * 80, 80, kk * 32 + lcx, lr, acc);
        __syncthreads();
    }

    // ============ epilogue-2: bias, row sum-of-squares, normalize, store =====
    {
        const float* b2 = p.bias2[lvl];
        float* rowsum = (float*)(dsm + RS_OFF);
#pragma unroll
        for (int hr = 0; hr < 2; hr++) {
            float part = 0.0f;
#pragma unroll
            for (int nb = 0; nb < 8; nb++) {
                const int c = warpN + (lid & 3) * 2 + nb * 8;
                float v0 = acc[nb][hr * 2]     + b2[c];
                float v1 = acc[nb][hr * 2 + 1] + b2[c + 1];
                acc[nb][hr * 2]     = v0;
                acc[nb][hr * 2 + 1] = v1;
                part += v0 * v0 + v1 * v1;
            }
            atomicAdd(&rowsum[warpM + hr * 8 + (lid >> 2)], part);
        }
        __syncthreads();
        float* O = p.out + (size_t)lvl * NROWS * NC;
#pragma unroll
        for (int hr = 0; hr < 2; hr++) {
            const int r = warpM + hr * 8 + (lid >> 2);
            const float sc = 1.0f / (sqrtf(rowsum[r]) + 1e-7f);
#pragma unroll
            for (int nb = 0; nb < 8; nb++) {
                const int c = warpN + (lid & 3) * 2 + nb * 8;
                float2 o;
                o.x = acc[nb][hr * 2]     * sc;
                o.y = acc[nb][hr * 2 + 1] * sc;
                *(float2*)(O + (size_t)(rowBase + r) * NC + c) = o;
            }
        }
    }
}

// ---------------- host ----------------
#define F0 67108864LL
#define F1 33554432LL
#define F2 16777216LL
#define W10 65536LL
#define W11 131072LL
#define W12 262144LL
#define SB  256LL

static inline bool ok_sz(long long actual, long long elems) {
    return actual == elems || actual == elems * 4 || actual == elems * 8;
}

extern "C" void kernel_launch(void* const* d_in, const int* in_sizes, int n_in,
                              void* d_out, int out_size) {
    (void)out_size;
    static const int CS[3]  = {256, 512, 1024};
    static const int HWS[3] = {128 * 128, 64 * 64, 32 * 32};
    static const size_t XOFF[3]  = {0, (size_t)4096 * 256, (size_t)4096 * 768};
    static const size_t W1OFF[3] = {0, (size_t)256 * 256, (size_t)256 * 768};

    static bool s_attr = false;
    if (!s_attr) {
        cudaFuncSetAttribute(mlp_kernel,
                             cudaFuncAttributeMaxDynamicSharedMemorySize, SMEM_TOTAL);
        s_attr = true;
    }

    static const int ORD_DICT[18]  = { 0,1,2,3,4,5,  6,7,8,9,10,11,  12,13,14,15,16,17 };
    static const int ORD_SIG[18]   = { 0,3,6,7,8,9,  1,4,10,11,12,13,  2,5,14,15,16,17 };
    static const int ORD_ALPHA[18] = { 6,9,12,0,15,3,  7,10,13,1,16,4,  8,11,14,2,17,5 };

    const long long featsz[3] = { F0, F1, F2 };
    const long long w1sz[3]   = { W10, W11, W12 };

    const int* cand[3] = { ORD_DICT, ORD_SIG, ORD_ALPHA };
    const int* ord = nullptr;
    for (int c = 0; c < 3 && !ord; c++) {
        bool ok = (n_in >= 18);
        for (int l = 0; l < 3 && ok; l++) {
            const int* m = cand[c] + 6 * l;
            ok = ok && ok_sz(in_sizes[m[0]], featsz[l])
                    && ok_sz(in_sizes[m[1]], SB)
                    && ok_sz(in_sizes[m[2]], w1sz[l])
                    && ok_sz(in_sizes[m[3]], SB)
                    && ok_sz(in_sizes[m[4]], W10)
                    && ok_sz(in_sizes[m[5]], SB);
        }
        if (ok) ord = cand[c];
    }

    int fi[3] = {-1,-1,-1}, pi[3] = {-1,-1,-1}, w1i[3] = {-1,-1,-1};
    int b1i[3] = {-1,-1,-1}, w2i[3] = {-1,-1,-1}, b2i[3] = {-1,-1,-1};
    if (ord) {
        for (int l = 0; l < 3; l++) {
            const int* m = ord + 6 * l;
            fi[l] = m[0]; pi[l] = m[1]; w1i[l] = m[2];
            b1i[l] = m[3]; w2i[l] = m[4]; b2i[l] = m[5];
        }
    } else {
        int any256 = -1, w2seen = 0, w10seen = 0;
        for (int i = 0; i < n_in; i++) {
            long long s = in_sizes[i];
            if      (ok_sz(s, F0))  fi[0] = i;
            else if (ok_sz(s, F1))  fi[1] = i;
            else if (ok_sz(s, F2))  fi[2] = i;
            else if (ok_sz(s, W11)) w1i[1] = i;
            else if (ok_sz(s, W12)) w1i[2] = i;
            else if (ok_sz(s, W10)) {
                if (!w10seen) { w1i[0] = i; w10seen = 1; }
                else if (w2seen < 3) w2i[w2seen++] = i;
            }
            else if (ok_sz(s, SB) && any256 < 0) any256 = i;
        }
        for (int l = 0; l < 3; l++) {
            if (fi[l] >= 0) {
                int nxt = fi[l] + 1;
                pi[l] = (nxt < n_in && ok_sz(in_sizes[nxt], SB)) ? nxt : any256;
            }
            b1i[l] = any256; b2i[l] = any256;
        }
    }
    for (int l = 0; l < 3; l++) {
        if (fi[l] < 0 || pi[l] < 0 || w1i[l] < 0 || b1i[l] < 0 ||
            w2i[l] < 0 || b2i[l] < 0) return;
    }

    PrepParams pp;
    MlpParams mp;
    for (int i = 0; i < 3; i++) {
        pp.feat[i] = (const float*)d_in[fi[i]];
        pp.pid[i]  = d_in[pi[i]];
        pp.W1[i]   = (const float*)d_in[w1i[i]];
        pp.W2[i]   = (const float*)d_in[w2i[i]];
        pp.C[i]    = CS[i];
        pp.HW[i]   = HWS[i];
        pp.xoff[i] = XOFF[i];
        pp.w1off[i] = W1OFF[i];

        mp.bias1[i] = (const float*)d_in[b1i[i]];
        mp.bias2[i] = (const float*)d_in[b2i[i]];
        mp.C[i]     = CS[i];
        mp.xoff[i]  = XOFF[i];
        mp.w1off[i] = W1OFF[i];
    }
    mp.out = (float*)d_out;

    // prep: 80 wcvt strips + 1536 gather blocks, LJF flat
    prep_kernel<<<1616, 256>>>(pp);

    mlp_kernel<<<192, 512, SMEM_TOTAL>>>(mp);
}